// round 15
// baseline (speedup 1.0000x reference)
#include <cuda_runtime.h>
#include <cuda_fp16.h>
#include <stdint.h>
#include <math.h>

// ---------------- problem constants ----------------
#define B_PTS    65536
#define C_DIM    2
#define V_OUT    3
#define D_DIM    64
#define K_CODES  1024
#define S_STAGES 4
#define H_DIM    1024
#define L_LAYERS 5
#define F_FREQ   25
#define IN_DIM   102       // C*(2F+1)
#define K0_PAD   128       // layer-0 K padded to 2 chunks of 64

// ---------------- GEMM tiling ----------------
#define BM 256
#define BN 128
#define BK 64
#define NSTAGE 3
#define THREADS 512
#define A_PLANE  32768                          // 256 rows x 128B (64 fp16)
#define B_PLANE  16384                          // 128 rows x 128B
#define STAGE_BYTES  (A_PLANE + 2*B_PLANE)      // 64KB (A single plane, W hi+lo)
#define SMEM_TOTAL   (NSTAGE*STAGE_BYTES)       // 192KB

// ---------------- device scratch (static, allocation-free; u32-backed fp16 planes) ----------------
__device__ __align__(256) uint32_t g_actA[(size_t)B_PTS * H_DIM / 2];   // fp16 activations ping
__device__ __align__(256) uint32_t g_actB[(size_t)B_PTS * H_DIM / 2];   // fp16 activations pong
__device__ __align__(256) uint32_t g_pe[(size_t)B_PTS * K0_PAD / 2];    // fp16 positional encoding
__device__ __align__(256) uint32_t g_w0t_h[H_DIM * K0_PAD / 2];
__device__ __align__(256) uint32_t g_w0t_l[H_DIM * K0_PAD / 2];
__device__ __align__(256) uint32_t g_wht_h[4ull * H_DIM * H_DIM / 2];
__device__ __align__(256) uint32_t g_wht_l[4ull * H_DIM * H_DIM / 2];
__device__ float g_bias[L_LAYERS * H_DIM];
__device__ float g_zsum[D_DIM];

// ---------------- PTX helpers (baseline sm_80+, valid on base sm_103) ----------------
__device__ __forceinline__ uint32_t smem_u32(const void* p) {
    uint32_t a;
    asm("{ .reg .u64 t; cvta.to.shared.u64 t, %1; cvt.u32.u64 %0, t; }" : "=r"(a) : "l"(p));
    return a;
}
__device__ __forceinline__ void cp_async16(uint32_t dst, const void* src) {
    asm volatile("cp.async.cg.shared.global [%0], [%1], 16;" :: "r"(dst), "l"(src) : "memory");
}
__device__ __forceinline__ void ldm_x4(uint32_t* r, uint32_t addr) {
    asm volatile("ldmatrix.sync.aligned.m8n8.x4.shared.b16 {%0,%1,%2,%3}, [%4];"
        : "=r"(r[0]), "=r"(r[1]), "=r"(r[2]), "=r"(r[3]) : "r"(addr));
}
__device__ __forceinline__ void mma_f16(float* c, const uint32_t* a, uint32_t b0, uint32_t b1) {
    asm volatile("mma.sync.aligned.m16n8k16.row.col.f32.f16.f16.f32 "
        "{%0,%1,%2,%3}, {%4,%5,%6,%7}, {%8,%9}, {%0,%1,%2,%3};"
        : "+f"(c[0]), "+f"(c[1]), "+f"(c[2]), "+f"(c[3])
        : "r"(a[0]), "r"(a[1]), "r"(a[2]), "r"(a[3]), "r"(b0), "r"(b1));
}

// ---------------- staging: one K-chunk of A + W(hi,lo) via cp.async ----------------
// planes are [rows][128B] with XOR swizzle: 16B chunk c of row stored at c ^ (row & 7).
__device__ __forceinline__ void stage_chunk(
    uint32_t stage_base,
    const __half* A, const __half* Wh, const __half* Wl,
    int bm, int bn, int kc, int K, int tid)
{
    // A plane: 256 rows x 8 granules = 2048 granules of 16B
    #pragma unroll
    for (int it = 0; it < 4; it++) {
        int g = tid + it * THREADS;
        int row = g >> 3, c = g & 7;
        uint32_t d = stage_base + (uint32_t)(row * 128 + ((c ^ (row & 7)) * 16));
        cp_async16(d, A + (size_t)(bm + row) * K + kc + c * 8);
    }
    // W planes: 128 rows x 8 granules = 1024 granules each
    #pragma unroll
    for (int it = 0; it < 2; it++) {
        int g = tid + it * THREADS;
        int row = g >> 3, c = g & 7;
        uint32_t d = stage_base + A_PLANE + (uint32_t)(row * 128 + ((c ^ (row & 7)) * 16));
        size_t boff = (size_t)(bn + row) * K + kc + c * 8;
        cp_async16(d,           Wh + boff);
        cp_async16(d + B_PLANE, Wl + boff);
    }
    asm volatile("cp.async.commit_group;" ::: "memory");
}

// ---------------- tensor-core MLP layer (mma.sync fp16, 2-term weight split) ----------------
// C[M,N] = relu(A @ W^T + bias); A fp16 [M,K] row-major; W = Wh+Wl fp16 [N,K] K-major.
// Mainloop: ONE barrier per chunk; refill of chunk i+2 issued BEFORE compute of chunk i.
// Safety: buf (i+2)%3 was last read during compute of chunk i-1; the barrier at the top
// of iteration i orders all of compute(i-1) before the refill stores.
__global__ void __launch_bounds__(THREADS, 1)
mlp_layer_kernel(const uint32_t* __restrict__ A32,
                 const uint32_t* __restrict__ Wh32, const uint32_t* __restrict__ Wl32,
                 const float* __restrict__ bias,
                 uint32_t* __restrict__ C32,
                 int K)
{
    extern __shared__ char smem[];
    uint32_t sb = smem_u32(smem);
    int tid  = threadIdx.x;
    int lane = tid & 31;
    int wid  = tid >> 5;                   // 0..15
    int wm = (wid >> 2) * 64;              // warp M offset (0,64,128,192)
    int wn = (wid & 3) * 32;               // warp N offset (0,32,64,96)
    int bm = blockIdx.y * BM;
    int bn = blockIdx.x * BN;
    int nch = K / BK;

    const __half* A  = (const __half*)A32;
    const __half* Wh = (const __half*)Wh32;
    const __half* Wl = (const __half*)Wl32;

    float acc[4][4][4];
    #pragma unroll
    for (int mi = 0; mi < 4; mi++)
        #pragma unroll
        for (int ni = 0; ni < 4; ni++)
            #pragma unroll
            for (int r = 0; r < 4; r++) acc[mi][ni][r] = 0.f;

    // prologue: stage 2 chunks (third buffer stays free for the first in-loop refill)
    stage_chunk(sb,               A, Wh, Wl, bm, bn, 0,  K, tid);
    if (nch > 1)
        stage_chunk(sb + STAGE_BYTES, A, Wh, Wl, bm, bn, BK, K, tid);

    int arow_l = lane & 15;       // row within 16-row tile
    int seg    = lane >> 4;       // k-segment half (0/1)

    for (int i = 0; i < nch; i++) {
        int s = i % NSTAGE;
        // chunk i must be complete; at most 1 newer group may stay pending
        if (i < nch - 1) asm volatile("cp.async.wait_group 1;" ::: "memory");
        else             asm volatile("cp.async.wait_group 0;" ::: "memory");
        __syncthreads();   // single barrier: orders compute(i-1) reads before refill below

        // refill next-next chunk into the buffer freed by compute(i-1); overlaps compute(i)
        if (i + 2 < nch)
            stage_chunk(sb + ((i + 2) % NSTAGE) * STAGE_BYTES, A, Wh, Wl,
                        bm, bn, (i + 2) * BK, K, tid);

        uint32_t aBase = sb + s * STAGE_BYTES;
        uint32_t bBase = aBase + A_PLANE;

        #pragma unroll
        for (int k16 = 0; k16 < 4; k16++) {
            uint32_t af[4][4];
            uint32_t bh[4][2], bl[4][2];
            #pragma unroll
            for (int mi = 0; mi < 4; mi++) {
                int row = wm + mi * 16 + arow_l;
                uint32_t c = (uint32_t)((k16 * 2 + seg) ^ (row & 7));
                ldm_x4(af[mi], aBase + (uint32_t)(row * 128) + c * 16);
            }
            #pragma unroll
            for (int ng = 0; ng < 2; ng++) {
                int row = wn + ng * 16 + arow_l;
                uint32_t c = (uint32_t)((k16 * 2 + seg) ^ (row & 7));
                uint32_t addr = bBase + (uint32_t)(row * 128) + c * 16;
                uint32_t t[4];
                ldm_x4(t, addr);
                bh[2 * ng][0] = t[0]; bh[2 * ng][1] = t[2];
                bh[2 * ng + 1][0] = t[1]; bh[2 * ng + 1][1] = t[3];
                ldm_x4(t, addr + B_PLANE);
                bl[2 * ng][0] = t[0]; bl[2 * ng][1] = t[2];
                bl[2 * ng + 1][0] = t[1]; bl[2 * ng + 1][1] = t[3];
            }
            #pragma unroll
            for (int mi = 0; mi < 4; mi++)
                #pragma unroll
                for (int ni = 0; ni < 4; ni++) {
                    mma_f16(acc[mi][ni], af[mi], bh[ni][0], bh[ni][1]);
                    mma_f16(acc[mi][ni], af[mi], bl[ni][0], bl[ni][1]);
                }
        }
    }

    // epilogue: bias + relu -> fp16, packed u32 stores
    int qr = lane >> 2;            // 0..7
    int qc = (lane & 3) * 2;       // 0,2,4,6
    #pragma unroll
    for (int mi = 0; mi < 4; mi++) {
        #pragma unroll
        for (int ni = 0; ni < 4; ni++) {
            int col = bn + wn + ni * 8 + qc;
            float b0 = bias[col], b1 = bias[col + 1];
            #pragma unroll
            for (int half = 0; half < 2; half++) {
                int row = bm + wm + mi * 16 + qr + half * 8;
                float v0 = fmaxf(acc[mi][ni][half * 2 + 0] + b0, 0.f);
                float v1 = fmaxf(acc[mi][ni][half * 2 + 1] + b1, 0.f);
                __half2 p = __floats2half2_rn(v0, v1);
                C32[(size_t)row * (H_DIM / 2) + (col >> 1)] = *reinterpret_cast<uint32_t*>(&p);
            }
        }
    }
}

// ---------------- RVQ: indices, loss, z_sum ----------------
__global__ void vq_kernel(const float* __restrict__ latents,
                          const int*   __restrict__ latent_idx,
                          const float* __restrict__ codebooks,
                          float* __restrict__ out_tail, int write_tail)
{
    __shared__ float s_img[S_STAGES][D_DIM];
    __shared__ float s_min[256];
    __shared__ int   s_mi[256];
    __shared__ int   s_idx[S_STAGES];

    int tid = threadIdx.x;
    int li = latent_idx[0];
    const float* img = latents + (size_t)li * S_STAGES * D_DIM;
    if (tid < S_STAGES * D_DIM) s_img[tid / D_DIM][tid % D_DIM] = img[tid];
    __syncthreads();

    for (int s = 0; s < S_STAGES; s++) {
        const float* z = s_img[s];
        float zz = 0.f;
        #pragma unroll
        for (int d = 0; d < D_DIM; d++) zz = fmaf(z[d], z[d], zz);
        float bmin = INFINITY; int bidx = 0x7fffffff;
        for (int k = tid; k < K_CODES; k += 256) {
            const float* e = codebooks + ((size_t)s * K_CODES + k) * D_DIM;
            float dot = 0.f, ee = 0.f;
            #pragma unroll
            for (int d = 0; d < D_DIM; d++) {
                float ev = e[d];
                dot = fmaf(z[d], ev, dot);
                ee  = fmaf(ev, ev, ee);
            }
            float dist = zz - 2.f * dot + ee;
            if (dist < bmin || (dist == bmin && k < bidx)) { bmin = dist; bidx = k; }
        }
        s_min[tid] = bmin; s_mi[tid] = bidx;
        __syncthreads();
        for (int off = 128; off > 0; off >>= 1) {
            if (tid < off) {
                float om = s_min[tid + off]; int oi = s_mi[tid + off];
                if (om < s_min[tid] || (om == s_min[tid] && oi < s_mi[tid])) {
                    s_min[tid] = om; s_mi[tid] = oi;
                }
            }
            __syncthreads();
        }
        if (tid == 0) s_idx[s] = s_mi[0];
        __syncthreads();
    }

    if (tid < D_DIM) {
        float v = 0.f;
        #pragma unroll
        for (int s = 0; s < S_STAGES; s++) v += s_img[s][tid];
        g_zsum[tid] = v;
    }
    if (tid == 0 && write_tail) {
        float loss = 0.f;
        for (int s = 0; s < S_STAGES; s++) {
            const float* e = codebooks + ((size_t)s * K_CODES + s_idx[s]) * D_DIM;
            float acc = 0.f;
            for (int d = 0; d < D_DIM; d++) {
                float df = e[d] - s_img[s][d];
                acc = fmaf(df, df, acc);
            }
            loss += 0.25f * (acc / (float)D_DIM);
        }
        for (int s = 0; s < S_STAGES; s++) out_tail[s] = (float)s_idx[s];
        out_tail[S_STAGES] = loss;
    }
}

// ---------------- combined bias: mod_b + zsum@mod_W + dec bias ----------------
__global__ void bias_kernel(const float* __restrict__ mod_W, const float* __restrict__ mod_b,
                            const float* __restrict__ dec_b0, const float* __restrict__ dec_bh)
{
    __shared__ float zs[D_DIM];
    int j = blockIdx.x * 256 + threadIdx.x;   // < 5120
    if (threadIdx.x < D_DIM) zs[threadIdx.x] = g_zsum[threadIdx.x];
    __syncthreads();
    int l = j >> 10, h = j & 1023;
    float acc = mod_b[j];
    #pragma unroll 8
    for (int d = 0; d < D_DIM; d++)
        acc = fmaf(zs[d], mod_W[((size_t)l * D_DIM + d) * H_DIM + h], acc);
    acc += (l == 0) ? dec_b0[h] : dec_bh[(size_t)(l - 1) * H_DIM + h];
    g_bias[j] = acc;
}

// ---------------- positional encoding -> fp16 plane (K padded to 128) ----------------
__global__ void pe_kernel(const float* __restrict__ coords)
{
    int idx = blockIdx.x * blockDim.x + threadIdx.x;
    if (idx >= B_PTS * K0_PAD) return;
    int b = idx >> 7, j = idx & 127;
    float v = 0.f;
    if (j < C_DIM) {
        v = coords[b * C_DIM + j];
    } else if (j < IN_DIM) {
        int r = j - C_DIM;
        int f = r >> 2;
        int t = (r >> 1) & 1;
        int c = r & 1;
        float fp = ldexpf(3.14159265358979323846f, f);
        float ang = coords[b * C_DIM + c] * fp;
        v = t ? cosf(ang) : sinf(ang);
    }
    ((__half*)g_pe)[idx] = __float2half_rn(v);
}

// ---------------- weight transpose + fp16 hi/lo split ----------------
// src [z][Ksrc][N] fp32 -> dst [z][N][Kpad] fp16 (zero-padded K)
__global__ void wtrans_kernel(const float* __restrict__ src, int Ksrc, int Kpad, int Ncols,
                              uint32_t* __restrict__ dst_h32, uint32_t* __restrict__ dst_l32)
{
    int z = blockIdx.z;
    const float* s = src + (size_t)z * Ksrc * Ncols;
    __half* dh = (__half*)dst_h32 + (size_t)z * Ncols * Kpad;
    __half* dl = (__half*)dst_l32 + (size_t)z * Ncols * Kpad;
    __shared__ float tile[32][33];
    int k0 = blockIdx.x * 32, n0 = blockIdx.y * 32;
    for (int yy = threadIdx.y; yy < 32; yy += 8) {
        int k = k0 + yy;
        tile[yy][threadIdx.x] = (k < Ksrc) ? s[(size_t)k * Ncols + n0 + threadIdx.x] : 0.f;
    }
    __syncthreads();
    for (int yy = threadIdx.y; yy < 32; yy += 8) {
        int n = n0 + yy, k = k0 + threadIdx.x;
        float v = tile[threadIdx.x][yy];
        __half h = __float2half_rn(v);
        dh[(size_t)n * Kpad + k] = h;
        dl[(size_t)n * Kpad + k] = __float2half_rn(v - __half2float(h));
    }
}

// ---------------- output projection (H -> 3) ----------------
__global__ void out_kernel(const uint32_t* __restrict__ h32in,
                           const float* __restrict__ Wout, const float* __restrict__ bout,
                           float* __restrict__ out)
{
    int b = blockIdx.x;
    int tid = threadIdx.x;
    const uint32_t* h32 = h32in + (size_t)b * (H_DIM / 2);
    float a0 = 0.f, a1 = 0.f, a2 = 0.f;
    for (int k2 = tid; k2 < H_DIM / 2; k2 += 128) {
        uint32_t hv = h32[k2];
        __half2 hp = *reinterpret_cast<const __half2*>(&hv);
        float2 hf = __half22float2(hp);
        int k = 2 * k2;
        a0 = fmaf(hf.x, Wout[k * 3 + 0], a0); a0 = fmaf(hf.y, Wout[(k + 1) * 3 + 0], a0);
        a1 = fmaf(hf.x, Wout[k * 3 + 1], a1); a1 = fmaf(hf.y, Wout[(k + 1) * 3 + 1], a1);
        a2 = fmaf(hf.x, Wout[k * 3 + 2], a2); a2 = fmaf(hf.y, Wout[(k + 1) * 3 + 2], a2);
    }
    #pragma unroll
    for (int off = 16; off; off >>= 1) {
        a0 += __shfl_down_sync(0xffffffffu, a0, off);
        a1 += __shfl_down_sync(0xffffffffu, a1, off);
        a2 += __shfl_down_sync(0xffffffffu, a2, off);
    }
    __shared__ float sr[4][3];
    int w = tid >> 5;
    if ((tid & 31) == 0) { sr[w][0] = a0; sr[w][1] = a1; sr[w][2] = a2; }
    __syncthreads();
    if (tid < V_OUT) {
        float v = bout[tid];
        #pragma unroll
        for (int ww = 0; ww < 4; ww++) v += sr[ww][tid];
        out[(size_t)b * V_OUT + tid] = v;
    }
}

// ---------------- launch ----------------
extern "C" void kernel_launch(void* const* d_in, const int* in_sizes, int n_in,
                              void* d_out, int out_size)
{
    const float* coords    = (const float*)d_in[0];
    const int*   latent_ix = (const int*)  d_in[1];
    const float* latents   = (const float*)d_in[2];
    const float* codebooks = (const float*)d_in[3];
    const float* mod_W     = (const float*)d_in[4];
    const float* mod_b     = (const float*)d_in[5];
    const float* dec_W0    = (const float*)d_in[6];
    const float* dec_b0    = (const float*)d_in[7];
    const float* dec_Wh    = (const float*)d_in[8];
    const float* dec_bh    = (const float*)d_in[9];
    const float* dec_Wout  = (const float*)d_in[10];
    const float* dec_bout  = (const float*)d_in[11];
    float* out = (float*)d_out;

    const int values_n = B_PTS * V_OUT;
    int write_tail = (out_size >= values_n + S_STAGES + 1) ? 1 : 0;

    cudaFuncSetAttribute(mlp_layer_kernel, cudaFuncAttributeMaxDynamicSharedMemorySize, SMEM_TOTAL);

    uint32_t *Aact, *Bact, *pe, *w0h, *w0l, *whh, *whl;
    float *bias;
    cudaGetSymbolAddress((void**)&Aact, g_actA);
    cudaGetSymbolAddress((void**)&Bact, g_actB);
    cudaGetSymbolAddress((void**)&pe,   g_pe);
    cudaGetSymbolAddress((void**)&w0h,  g_w0t_h);
    cudaGetSymbolAddress((void**)&w0l,  g_w0t_l);
    cudaGetSymbolAddress((void**)&whh,  g_wht_h);
    cudaGetSymbolAddress((void**)&whl,  g_wht_l);
    cudaGetSymbolAddress((void**)&bias, g_bias);

    // prep
    vq_kernel<<<1, 256>>>(latents, latent_ix, codebooks, out + values_n, write_tail);
    bias_kernel<<<20, 256>>>(mod_W, mod_b, dec_b0, dec_bh);
    pe_kernel<<<(B_PTS * K0_PAD + 255) / 256, 256>>>(coords);
    {
        dim3 blk(32, 8);
        wtrans_kernel<<<dim3(K0_PAD / 32, H_DIM / 32, 1), blk>>>(dec_W0, IN_DIM, K0_PAD, H_DIM, w0h, w0l);
        wtrans_kernel<<<dim3(H_DIM / 32, H_DIM / 32, 4), blk>>>(dec_Wh, H_DIM, H_DIM, H_DIM, whh, whl);
    }

    dim3 grid(H_DIM / BN, B_PTS / BM);   // (8, 256) = 2048 CTAs
    size_t WH = (size_t)H_DIM * H_DIM / 2;

    // layer 0: pe(128) @ W0^T -> actA
    mlp_layer_kernel<<<grid, THREADS, SMEM_TOTAL>>>(pe, w0h, w0l, bias + 0 * H_DIM, Aact, K0_PAD);
    // hidden layers 1..4 (ping-pong actA <-> actB)
    mlp_layer_kernel<<<grid, THREADS, SMEM_TOTAL>>>(Aact, whh + 0 * WH, whl + 0 * WH, bias + 1 * H_DIM, Bact, H_DIM);
    mlp_layer_kernel<<<grid, THREADS, SMEM_TOTAL>>>(Bact, whh + 1 * WH, whl + 1 * WH, bias + 2 * H_DIM, Aact, H_DIM);
    mlp_layer_kernel<<<grid, THREADS, SMEM_TOTAL>>>(Aact, whh + 2 * WH, whl + 2 * WH, bias + 3 * H_DIM, Bact, H_DIM);
    mlp_layer_kernel<<<grid, THREADS, SMEM_TOTAL>>>(Bact, whh + 3 * WH, whl + 3 * WH, bias + 4 * H_DIM, Aact, H_DIM);
    // output projection
    out_kernel<<<B_PTS, 128>>>(Aact, dec_Wout, dec_bout, out);
}

// round 16
// speedup vs baseline: 1.1360x; 1.1360x over previous
#include <cuda_runtime.h>
#include <cuda_fp16.h>
#include <stdint.h>
#include <math.h>

// ---------------- problem constants ----------------
#define B_PTS    65536
#define C_DIM    2
#define V_OUT    3
#define D_DIM    64
#define K_CODES  1024
#define S_STAGES 4
#define H_DIM    1024
#define L_LAYERS 5
#define F_FREQ   25
#define IN_DIM   102       // C*(2F+1)
#define K0_PAD   128       // layer-0 K padded to 2 chunks of 64

// ---------------- GEMM tiling ----------------
#define BM 128
#define BN 128
#define BK 64
#define NSTAGE 2
#define THREADS 256
#define A_PLANE  16384                          // 128 rows x 128B (64 fp16)
#define B_PLANE  16384                          // 128 rows x 128B
#define STAGE_BYTES  (A_PLANE + 2*B_PLANE)      // 48KB (A single plane, W hi+lo)
#define SMEM_TOTAL   (NSTAGE*STAGE_BYTES)       // 96KB -> 2 CTAs per SM

// ---------------- device scratch (static, allocation-free; u32-backed fp16 planes) ----------------
__device__ __align__(256) uint32_t g_actA[(size_t)B_PTS * H_DIM / 2];   // fp16 activations ping
__device__ __align__(256) uint32_t g_actB[(size_t)B_PTS * H_DIM / 2];   // fp16 activations pong
__device__ __align__(256) uint32_t g_pe[(size_t)B_PTS * K0_PAD / 2];    // fp16 positional encoding
__device__ __align__(256) uint32_t g_w0t_h[H_DIM * K0_PAD / 2];
__device__ __align__(256) uint32_t g_w0t_l[H_DIM * K0_PAD / 2];
__device__ __align__(256) uint32_t g_wht_h[4ull * H_DIM * H_DIM / 2];
__device__ __align__(256) uint32_t g_wht_l[4ull * H_DIM * H_DIM / 2];
__device__ float g_bias[L_LAYERS * H_DIM];
__device__ float g_zsum[D_DIM];

// ---------------- PTX helpers (baseline sm_80+, valid on base sm_103) ----------------
__device__ __forceinline__ uint32_t smem_u32(const void* p) {
    uint32_t a;
    asm("{ .reg .u64 t; cvta.to.shared.u64 t, %1; cvt.u32.u64 %0, t; }" : "=r"(a) : "l"(p));
    return a;
}
__device__ __forceinline__ void cp_async16(uint32_t dst, const void* src) {
    asm volatile("cp.async.cg.shared.global [%0], [%1], 16;" :: "r"(dst), "l"(src) : "memory");
}
__device__ __forceinline__ void ldm_x4(uint32_t* r, uint32_t addr) {
    asm volatile("ldmatrix.sync.aligned.m8n8.x4.shared.b16 {%0,%1,%2,%3}, [%4];"
        : "=r"(r[0]), "=r"(r[1]), "=r"(r[2]), "=r"(r[3]) : "r"(addr));
}
__device__ __forceinline__ void mma_f16(float* c, const uint32_t* a, uint32_t b0, uint32_t b1) {
    asm volatile("mma.sync.aligned.m16n8k16.row.col.f32.f16.f16.f32 "
        "{%0,%1,%2,%3}, {%4,%5,%6,%7}, {%8,%9}, {%0,%1,%2,%3};"
        : "+f"(c[0]), "+f"(c[1]), "+f"(c[2]), "+f"(c[3])
        : "r"(a[0]), "r"(a[1]), "r"(a[2]), "r"(a[3]), "r"(b0), "r"(b1));
}

// ---------------- staging: one K-chunk of A + W(hi,lo) via cp.async ----------------
// planes are [rows][128B] with XOR swizzle: 16B chunk c of row stored at c ^ (row & 7).
__device__ __forceinline__ void stage_chunk(
    uint32_t stage_base,
    const __half* A, const __half* Wh, const __half* Wl,
    int bm, int bn, int kc, int K, int tid)
{
    // A plane: 128 rows x 8 granules = 1024 granules of 16B
    #pragma unroll
    for (int it = 0; it < 4; it++) {
        int g = tid + it * THREADS;
        int row = g >> 3, c = g & 7;
        uint32_t d = stage_base + (uint32_t)(row * 128 + ((c ^ (row & 7)) * 16));
        cp_async16(d, A + (size_t)(bm + row) * K + kc + c * 8);
    }
    // W planes: 128 rows x 8 granules = 1024 granules each
    #pragma unroll
    for (int it = 0; it < 4; it++) {
        int g = tid + it * THREADS;
        int row = g >> 3, c = g & 7;
        uint32_t d = stage_base + A_PLANE + (uint32_t)(row * 128 + ((c ^ (row & 7)) * 16));
        size_t boff = (size_t)(bn + row) * K + kc + c * 8;
        cp_async16(d,           Wh + boff);
        cp_async16(d + B_PLANE, Wl + boff);
    }
    asm volatile("cp.async.commit_group;" ::: "memory");
}

// ---------------- tensor-core MLP layer (mma.sync fp16, 2-term weight split) ----------------
// C[M,N] = relu(A @ W^T + bias); A fp16 [M,K] row-major; W = Wh+Wl fp16 [N,K] K-major.
// R14 mainloop structure (wait -> sync -> compute -> sync -> refill), 2 CTAs/SM.
__global__ void __launch_bounds__(THREADS, 2)
mlp_layer_kernel(const uint32_t* __restrict__ A32,
                 const uint32_t* __restrict__ Wh32, const uint32_t* __restrict__ Wl32,
                 const float* __restrict__ bias,
                 uint32_t* __restrict__ C32,
                 int K)
{
    extern __shared__ char smem[];
    uint32_t sb = smem_u32(smem);
    int tid  = threadIdx.x;
    int lane = tid & 31;
    int wid  = tid >> 5;                   // 0..7
    int wm = (wid >> 2) * 64;              // warp M offset (0,64)
    int wn = (wid & 3) * 32;               // warp N offset (0,32,64,96)
    int bm = blockIdx.y * BM;
    int bn = blockIdx.x * BN;
    int nch = K / BK;

    const __half* A  = (const __half*)A32;
    const __half* Wh = (const __half*)Wh32;
    const __half* Wl = (const __half*)Wl32;

    float acc[4][4][4];
    #pragma unroll
    for (int mi = 0; mi < 4; mi++)
        #pragma unroll
        for (int ni = 0; ni < 4; ni++)
            #pragma unroll
            for (int r = 0; r < 4; r++) acc[mi][ni][r] = 0.f;

    // prologue: fill both stages
    stage_chunk(sb,               A, Wh, Wl, bm, bn, 0,  K, tid);
    if (nch > 1)
        stage_chunk(sb + STAGE_BYTES, A, Wh, Wl, bm, bn, BK, K, tid);

    int arow_l = lane & 15;       // row within 16-row tile
    int seg    = lane >> 4;       // k-segment half (0/1)

    for (int i = 0; i < nch; i++) {
        int s = i & 1;
        if (i == nch - 1) asm volatile("cp.async.wait_group 0;" ::: "memory");
        else              asm volatile("cp.async.wait_group 1;" ::: "memory");
        __syncthreads();

        uint32_t aBase = sb + s * STAGE_BYTES;
        uint32_t bBase = aBase + A_PLANE;

        #pragma unroll
        for (int k16 = 0; k16 < 4; k16++) {
            uint32_t af[4][4];
            uint32_t bh[4][2], bl[4][2];
            #pragma unroll
            for (int mi = 0; mi < 4; mi++) {
                int row = wm + mi * 16 + arow_l;
                uint32_t c = (uint32_t)((k16 * 2 + seg) ^ (row & 7));
                ldm_x4(af[mi], aBase + (uint32_t)(row * 128) + c * 16);
            }
            #pragma unroll
            for (int ng = 0; ng < 2; ng++) {
                int row = wn + ng * 16 + arow_l;
                uint32_t c = (uint32_t)((k16 * 2 + seg) ^ (row & 7));
                uint32_t addr = bBase + (uint32_t)(row * 128) + c * 16;
                uint32_t t[4];
                ldm_x4(t, addr);
                bh[2 * ng][0] = t[0]; bh[2 * ng][1] = t[2];
                bh[2 * ng + 1][0] = t[1]; bh[2 * ng + 1][1] = t[3];
                ldm_x4(t, addr + B_PLANE);
                bl[2 * ng][0] = t[0]; bl[2 * ng][1] = t[2];
                bl[2 * ng + 1][0] = t[1]; bl[2 * ng + 1][1] = t[3];
            }
            #pragma unroll
            for (int mi = 0; mi < 4; mi++)
                #pragma unroll
                for (int ni = 0; ni < 4; ni++) {
                    mma_f16(acc[mi][ni], af[mi], bh[ni][0], bh[ni][1]);
                    mma_f16(acc[mi][ni], af[mi], bl[ni][0], bl[ni][1]);
                }
        }
        __syncthreads();   // all warps done reading buffer s before refill

        if (i + NSTAGE < nch)
            stage_chunk(sb + s * STAGE_BYTES, A, Wh, Wl, bm, bn, (i + NSTAGE) * BK, K, tid);
    }

    // epilogue: bias + relu -> fp16, packed u32 stores
    int qr = lane >> 2;            // 0..7
    int qc = (lane & 3) * 2;       // 0,2,4,6
    #pragma unroll
    for (int mi = 0; mi < 4; mi++) {
        #pragma unroll
        for (int ni = 0; ni < 4; ni++) {
            int col = bn + wn + ni * 8 + qc;
            float b0 = bias[col], b1 = bias[col + 1];
            #pragma unroll
            for (int half = 0; half < 2; half++) {
                int row = bm + wm + mi * 16 + qr + half * 8;
                float v0 = fmaxf(acc[mi][ni][half * 2 + 0] + b0, 0.f);
                float v1 = fmaxf(acc[mi][ni][half * 2 + 1] + b1, 0.f);
                __half2 p = __floats2half2_rn(v0, v1);
                C32[(size_t)row * (H_DIM / 2) + (col >> 1)] = *reinterpret_cast<uint32_t*>(&p);
            }
        }
    }
}

// ---------------- RVQ: indices, loss, z_sum ----------------
__global__ void vq_kernel(const float* __restrict__ latents,
                          const int*   __restrict__ latent_idx,
                          const float* __restrict__ codebooks,
                          float* __restrict__ out_tail, int write_tail)
{
    __shared__ float s_img[S_STAGES][D_DIM];
    __shared__ float s_min[256];
    __shared__ int   s_mi[256];
    __shared__ int   s_idx[S_STAGES];

    int tid = threadIdx.x;
    int li = latent_idx[0];
    const float* img = latents + (size_t)li * S_STAGES * D_DIM;
    if (tid < S_STAGES * D_DIM) s_img[tid / D_DIM][tid % D_DIM] = img[tid];
    __syncthreads();

    for (int s = 0; s < S_STAGES; s++) {
        const float* z = s_img[s];
        float zz = 0.f;
        #pragma unroll
        for (int d = 0; d < D_DIM; d++) zz = fmaf(z[d], z[d], zz);
        float bmin = INFINITY; int bidx = 0x7fffffff;
        for (int k = tid; k < K_CODES; k += 256) {
            const float* e = codebooks + ((size_t)s * K_CODES + k) * D_DIM;
            float dot = 0.f, ee = 0.f;
            #pragma unroll
            for (int d = 0; d < D_DIM; d++) {
                float ev = e[d];
                dot = fmaf(z[d], ev, dot);
                ee  = fmaf(ev, ev, ee);
            }
            float dist = zz - 2.f * dot + ee;
            if (dist < bmin || (dist == bmin && k < bidx)) { bmin = dist; bidx = k; }
        }
        s_min[tid] = bmin; s_mi[tid] = bidx;
        __syncthreads();
        for (int off = 128; off > 0; off >>= 1) {
            if (tid < off) {
                float om = s_min[tid + off]; int oi = s_mi[tid + off];
                if (om < s_min[tid] || (om == s_min[tid] && oi < s_mi[tid])) {
                    s_min[tid] = om; s_mi[tid] = oi;
                }
            }
            __syncthreads();
        }
        if (tid == 0) s_idx[s] = s_mi[0];
        __syncthreads();
    }

    if (tid < D_DIM) {
        float v = 0.f;
        #pragma unroll
        for (int s = 0; s < S_STAGES; s++) v += s_img[s][tid];
        g_zsum[tid] = v;
    }
    if (tid == 0 && write_tail) {
        float loss = 0.f;
        for (int s = 0; s < S_STAGES; s++) {
            const float* e = codebooks + ((size_t)s * K_CODES + s_idx[s]) * D_DIM;
            float acc = 0.f;
            for (int d = 0; d < D_DIM; d++) {
                float df = e[d] - s_img[s][d];
                acc = fmaf(df, df, acc);
            }
            loss += 0.25f * (acc / (float)D_DIM);
        }
        for (int s = 0; s < S_STAGES; s++) out_tail[s] = (float)s_idx[s];
        out_tail[S_STAGES] = loss;
    }
}

// ---------------- combined bias: mod_b + zsum@mod_W + dec bias ----------------
__global__ void bias_kernel(const float* __restrict__ mod_W, const float* __restrict__ mod_b,
                            const float* __restrict__ dec_b0, const float* __restrict__ dec_bh)
{
    __shared__ float zs[D_DIM];
    int j = blockIdx.x * 256 + threadIdx.x;   // < 5120
    if (threadIdx.x < D_DIM) zs[threadIdx.x] = g_zsum[threadIdx.x];
    __syncthreads();
    int l = j >> 10, h = j & 1023;
    float acc = mod_b[j];
    #pragma unroll 8
    for (int d = 0; d < D_DIM; d++)
        acc = fmaf(zs[d], mod_W[((size_t)l * D_DIM + d) * H_DIM + h], acc);
    acc += (l == 0) ? dec_b0[h] : dec_bh[(size_t)(l - 1) * H_DIM + h];
    g_bias[j] = acc;
}

// ---------------- positional encoding -> fp16 plane (K padded to 128) ----------------
__global__ void pe_kernel(const float* __restrict__ coords)
{
    int idx = blockIdx.x * blockDim.x + threadIdx.x;
    if (idx >= B_PTS * K0_PAD) return;
    int b = idx >> 7, j = idx & 127;
    float v = 0.f;
    if (j < C_DIM) {
        v = coords[b * C_DIM + j];
    } else if (j < IN_DIM) {
        int r = j - C_DIM;
        int f = r >> 2;
        int t = (r >> 1) & 1;
        int c = r & 1;
        float fp = ldexpf(3.14159265358979323846f, f);
        float ang = coords[b * C_DIM + c] * fp;
        v = t ? cosf(ang) : sinf(ang);
    }
    ((__half*)g_pe)[idx] = __float2half_rn(v);
}

// ---------------- weight transpose + fp16 hi/lo split ----------------
// src [z][Ksrc][N] fp32 -> dst [z][N][Kpad] fp16 (zero-padded K)
__global__ void wtrans_kernel(const float* __restrict__ src, int Ksrc, int Kpad, int Ncols,
                              uint32_t* __restrict__ dst_h32, uint32_t* __restrict__ dst_l32)
{
    int z = blockIdx.z;
    const float* s = src + (size_t)z * Ksrc * Ncols;
    __half* dh = (__half*)dst_h32 + (size_t)z * Ncols * Kpad;
    __half* dl = (__half*)dst_l32 + (size_t)z * Ncols * Kpad;
    __shared__ float tile[32][33];
    int k0 = blockIdx.x * 32, n0 = blockIdx.y * 32;
    for (int yy = threadIdx.y; yy < 32; yy += 8) {
        int k = k0 + yy;
        tile[yy][threadIdx.x] = (k < Ksrc) ? s[(size_t)k * Ncols + n0 + threadIdx.x] : 0.f;
    }
    __syncthreads();
    for (int yy = threadIdx.y; yy < 32; yy += 8) {
        int n = n0 + yy, k = k0 + threadIdx.x;
        float v = tile[threadIdx.x][yy];
        __half h = __float2half_rn(v);
        dh[(size_t)n * Kpad + k] = h;
        dl[(size_t)n * Kpad + k] = __float2half_rn(v - __half2float(h));
    }
}

// ---------------- output projection (H -> 3) ----------------
__global__ void out_kernel(const uint32_t* __restrict__ h32in,
                           const float* __restrict__ Wout, const float* __restrict__ bout,
                           float* __restrict__ out)
{
    int b = blockIdx.x;
    int tid = threadIdx.x;
    const uint32_t* h32 = h32in + (size_t)b * (H_DIM / 2);
    float a0 = 0.f, a1 = 0.f, a2 = 0.f;
    for (int k2 = tid; k2 < H_DIM / 2; k2 += 128) {
        uint32_t hv = h32[k2];
        __half2 hp = *reinterpret_cast<const __half2*>(&hv);
        float2 hf = __half22float2(hp);
        int k = 2 * k2;
        a0 = fmaf(hf.x, Wout[k * 3 + 0], a0); a0 = fmaf(hf.y, Wout[(k + 1) * 3 + 0], a0);
        a1 = fmaf(hf.x, Wout[k * 3 + 1], a1); a1 = fmaf(hf.y, Wout[(k + 1) * 3 + 1], a1);
        a2 = fmaf(hf.x, Wout[k * 3 + 2], a2); a2 = fmaf(hf.y, Wout[(k + 1) * 3 + 2], a2);
    }
    #pragma unroll
    for (int off = 16; off; off >>= 1) {
        a0 += __shfl_down_sync(0xffffffffu, a0, off);
        a1 += __shfl_down_sync(0xffffffffu, a1, off);
        a2 += __shfl_down_sync(0xffffffffu, a2, off);
    }
    __shared__ float sr[4][3];
    int w = tid >> 5;
    if ((tid & 31) == 0) { sr[w][0] = a0; sr[w][1] = a1; sr[w][2] = a2; }
    __syncthreads();
    if (tid < V_OUT) {
        float v = bout[tid];
        #pragma unroll
        for (int ww = 0; ww < 4; ww++) v += sr[ww][tid];
        out[(size_t)b * V_OUT + tid] = v;
    }
}

// ---------------- launch ----------------
extern "C" void kernel_launch(void* const* d_in, const int* in_sizes, int n_in,
                              void* d_out, int out_size)
{
    const float* coords    = (const float*)d_in[0];
    const int*   latent_ix = (const int*)  d_in[1];
    const float* latents   = (const float*)d_in[2];
    const float* codebooks = (const float*)d_in[3];
    const float* mod_W     = (const float*)d_in[4];
    const float* mod_b     = (const float*)d_in[5];
    const float* dec_W0    = (const float*)d_in[6];
    const float* dec_b0    = (const float*)d_in[7];
    const float* dec_Wh    = (const float*)d_in[8];
    const float* dec_bh    = (const float*)d_in[9];
    const float* dec_Wout  = (const float*)d_in[10];
    const float* dec_bout  = (const float*)d_in[11];
    float* out = (float*)d_out;

    const int values_n = B_PTS * V_OUT;
    int write_tail = (out_size >= values_n + S_STAGES + 1) ? 1 : 0;

    cudaFuncSetAttribute(mlp_layer_kernel, cudaFuncAttributeMaxDynamicSharedMemorySize, SMEM_TOTAL);

    uint32_t *Aact, *Bact, *pe, *w0h, *w0l, *whh, *whl;
    float *bias;
    cudaGetSymbolAddress((void**)&Aact, g_actA);
    cudaGetSymbolAddress((void**)&Bact, g_actB);
    cudaGetSymbolAddress((void**)&pe,   g_pe);
    cudaGetSymbolAddress((void**)&w0h,  g_w0t_h);
    cudaGetSymbolAddress((void**)&w0l,  g_w0t_l);
    cudaGetSymbolAddress((void**)&whh,  g_wht_h);
    cudaGetSymbolAddress((void**)&whl,  g_wht_l);
    cudaGetSymbolAddress((void**)&bias, g_bias);

    // prep
    vq_kernel<<<1, 256>>>(latents, latent_ix, codebooks, out + values_n, write_tail);
    bias_kernel<<<20, 256>>>(mod_W, mod_b, dec_b0, dec_bh);
    pe_kernel<<<(B_PTS * K0_PAD + 255) / 256, 256>>>(coords);
    {
        dim3 blk(32, 8);
        wtrans_kernel<<<dim3(K0_PAD / 32, H_DIM / 32, 1), blk>>>(dec_W0, IN_DIM, K0_PAD, H_DIM, w0h, w0l);
        wtrans_kernel<<<dim3(H_DIM / 32, H_DIM / 32, 4), blk>>>(dec_Wh, H_DIM, H_DIM, H_DIM, whh, whl);
    }

    dim3 grid(H_DIM / BN, B_PTS / BM);   // (8, 512) = 4096 CTAs
    size_t WH = (size_t)H_DIM * H_DIM / 2;

    // layer 0: pe(128) @ W0^T -> actA
    mlp_layer_kernel<<<grid, THREADS, SMEM_TOTAL>>>(pe, w0h, w0l, bias + 0 * H_DIM, Aact, K0_PAD);
    // hidden layers 1..4 (ping-pong actA <-> actB)
    mlp_layer_kernel<<<grid, THREADS, SMEM_TOTAL>>>(Aact, whh + 0 * WH, whl + 0 * WH, bias + 1 * H_DIM, Bact, H_DIM);
    mlp_layer_kernel<<<grid, THREADS, SMEM_TOTAL>>>(Bact, whh + 1 * WH, whl + 1 * WH, bias + 2 * H_DIM, Aact, H_DIM);
    mlp_layer_kernel<<<grid, THREADS, SMEM_TOTAL>>>(Aact, whh + 2 * WH, whl + 2 * WH, bias + 3 * H_DIM, Bact, H_DIM);
    mlp_layer_kernel<<<grid, THREADS, SMEM_TOTAL>>>(Bact, whh + 3 * WH, whl + 3 * WH, bias + 4 * H_DIM, Aact, H_DIM);
    // output projection
    out_kernel<<<B_PTS, 128>>>(Aact, dec_Wout, dec_bout, out);
}